// round 12
// baseline (speedup 1.0000x reference)
#include <cuda_runtime.h>
#include <cuda_fp16.h>
#include <cstdint>

// ---------------------------------------------------------------------------
// NodePredictor: y[b,n,:] = x[b,n,:] @ W[n] + b[n], out = y reshaped [B, N*DOUT]
// B=2048, N=64, DIN=DOUT=512, fp32. sm_100 legacy path.
//
// R12 = R11 (fp16 m16n8k16 MMA, 2 tiles/CTA, ks rotation, 3 stages) with the
// x->fp16 prepass FUSED into the GEMM's A staging (LDG.128 -> cvt.f16x2 ->
// STS.128, R6-proven schedule: load held across the 4-ks compute window).
// Deletes the 64us x_convert kernel and the 128MB g_Xh scratch.
// ---------------------------------------------------------------------------

static constexpr int B_DIM   = 2048;
static constexpr int N_NODES = 64;
static constexpr int DIN     = 512;
static constexpr int DOUT    = 512;
static constexpr int OUT_W   = N_NODES * DOUT;   // 32768

static constexpr int TILE_M  = 128;
static constexpr int TILE_N  = 128;
static constexpr int TILE_K  = 64;               // 64 halfs = 128 B row
static constexpr int K_ITERS = DIN / TILE_K;     // 8
static constexpr int THREADS = 256;
static constexpr int STAGES  = 3;

static constexpr int A_BYTES = TILE_M * 128;     // 16 KB
static constexpr int STAGE_BYTES = 32768;        // A 16KB + B 16KB
static constexpr int SMEM_BIAS   = STAGES * STAGE_BYTES;          // 98304
static constexpr int SMEM_TOTAL  = SMEM_BIAS + 2 * TILE_N * 4;    // 99328

// scratch: W^T pre-converted to fp16 (RNE), 32 MB
__device__ __half g_Wh[(size_t)N_NODES * DOUT * DIN];

// ---------------------------------------------------------------------------
__device__ __forceinline__ uint32_t smem_u32(const void* p) {
    uint32_t a;
    asm("{ .reg .u64 t; cvta.to.shared.u64 t, %1; cvt.u32.u64 %0, t; }" : "=r"(a) : "l"(p));
    return a;
}
__device__ __forceinline__ uint32_t sw128(uint32_t off) {
    return off ^ ((off >> 3) & 0x70u);
}
__device__ __forceinline__ uint32_t h2(float a, float b) {
    __half2 h = __floats2half2_rn(a, b);
    return *reinterpret_cast<uint32_t*>(&h);
}
__device__ __forceinline__ void cp_async16(uint32_t smem_dst, const void* gmem_src) {
    asm volatile("cp.async.cg.shared.global [%0], [%1], 16;"
                 :: "r"(smem_dst), "l"(gmem_src) : "memory");
}
__device__ __forceinline__ void cp_commit() {
    asm volatile("cp.async.commit_group;" ::: "memory");
}
template <int N>
__device__ __forceinline__ void cp_wait() {
    asm volatile("cp.async.wait_group %0;" :: "n"(N) : "memory");
}
__device__ __forceinline__ void ldsm_x4(uint32_t* r, uint32_t addr) {
    asm volatile("ldmatrix.sync.aligned.m8n8.x4.shared.b16 {%0,%1,%2,%3}, [%4];"
                 : "=r"(r[0]), "=r"(r[1]), "=r"(r[2]), "=r"(r[3]) : "r"(addr));
}
__device__ __forceinline__ void mma_f16(float* c, const uint32_t* a, uint32_t b0, uint32_t b1) {
    asm volatile(
        "mma.sync.aligned.m16n8k16.row.col.f32.f16.f16.f32 "
        "{%0,%1,%2,%3}, {%4,%5,%6,%7}, {%8,%9}, {%0,%1,%2,%3};"
        : "+f"(c[0]), "+f"(c[1]), "+f"(c[2]), "+f"(c[3])
        : "r"(a[0]), "r"(a[1]), "r"(a[2]), "r"(a[3]), "r"(b0), "r"(b1));
}
__device__ __forceinline__ void sts128(uint32_t addr, uint32_t r0, uint32_t r1,
                                       uint32_t r2, uint32_t r3) {
    asm volatile("st.shared.v4.b32 [%0], {%1, %2, %3, %4};"
                 :: "r"(addr), "r"(r0), "r"(r1), "r"(r2), "r"(r3) : "memory");
}

// ---------------------------------------------------------------------------
// Pre-pass: g_Wh[n][o][i] = half(W[n][i][o])  (RNE)
// ---------------------------------------------------------------------------
__global__ void wt_transpose_kernel(const float* __restrict__ W) {
    __shared__ float tile[32][33];
    const int n  = blockIdx.z;
    const int i0 = blockIdx.x * 32;
    const int o0 = blockIdx.y * 32;
    const int tx = threadIdx.x, ty = threadIdx.y;   // 32 x 8

    const float* src = W + ((size_t)n * DIN + i0) * DOUT + o0;
#pragma unroll
    for (int r = 0; r < 32; r += 8)
        tile[ty + r][tx] = src[(size_t)(ty + r) * DOUT + tx];
    __syncthreads();

    __half* dst = g_Wh + ((size_t)n * DOUT + o0) * DIN + i0;
#pragma unroll
    for (int r = 0; r < 32; r += 8)
        dst[(size_t)(ty + r) * DIN + tx] = __float2half_rn(tile[tx][ty + r]);
}

// ---------------------------------------------------------------------------
// Main GEMM: CTA handles TWO [128M x 128N] tiles (same node+mt, nt pair).
// 8 warps 2x4, warptile 64x32, fp16 MMA m16n8k16. A converted in staging.
// ---------------------------------------------------------------------------
__global__ __launch_bounds__(THREADS, 2)
void node_gemm_kernel(const float* __restrict__ x, const float* __restrict__ bias,
                      float* __restrict__ out) {
    extern __shared__ char smem[];
    const uint32_t sbase = smem_u32(smem);
    const int tid  = threadIdx.x;
    const int wid  = tid >> 5;
    const int lane = tid & 31;

    // block decode: ntp fastest, then mt, then node
    const int bx  = blockIdx.x;
    const int n   = bx >> 5;
    const int mt  = (bx >> 1) & 15;
    const int ntp = bx & 1;                 // nt pair: tiles ntp*2, ntp*2+1
    const int m_base  = mt * TILE_M;
    const int o_base0 = (ntp * 2) * TILE_N;

    // both tiles' biases -> smem
    {
        const int t = tid >> 7;             // 0 or 1
        const int c = tid & 127;
        reinterpret_cast<float*>(smem + SMEM_BIAS)[t * TILE_N + c] =
            bias[n * DOUT + o_base0 + t * TILE_N + c];
    }

    // ---- staging: thread t -> row t/2, fp16 16B-chunks (t&1)*4..+3
    // A slice per thread: 32 fp32 (128B) -> 32 fp16 (64B, 4 chunks)
    const int st_row = tid >> 1;
    const int st_cb  = (tid & 1) * 4;                     // chunk base
    const float*  a_src = x + ((size_t)(m_base + st_row) * N_NODES + n) * DIN + st_cb * 8;
    const __half* b_src0 = g_Wh + ((size_t)(n * DOUT + o_base0 + st_row)) * DIN + st_cb * 8;
    uint32_t st_dst[4];
#pragma unroll
    for (int j = 0; j < 4; ++j)
        st_dst[j] = sw128((uint32_t)st_row * 128u + (uint32_t)(st_cb + j) * 16u);

    // B: one cp.async commit group per stage (pre-converted fp16)
    auto issue_b = [&](int stage, int kc, const __half* b_src) {
        const uint32_t bs = sbase + stage * STAGE_BYTES + A_BYTES;
        const __half* bp = b_src + kc * TILE_K;
#pragma unroll
        for (int j = 0; j < 4; ++j) cp_async16(bs + st_dst[j], bp + j * 8);
        cp_commit();
    };
    // A: LDG 8xfloat4 (held in regs), then cvt+STS
    auto ldg_a = [&](float4* v, int kc) {
        const float4* ap = reinterpret_cast<const float4*>(a_src + kc * TILE_K);
#pragma unroll
        for (int j = 0; j < 8; ++j) v[j] = ap[j];
    };
    auto sts_a = [&](int stage, const float4* v) {
        const uint32_t as = sbase + stage * STAGE_BYTES;
#pragma unroll
        for (int j = 0; j < 4; ++j) {
            const float4 p = v[2 * j], q = v[2 * j + 1];
            sts128(as + st_dst[j], h2(p.x, p.y), h2(p.z, p.w),
                   h2(q.x, q.y), h2(q.z, q.w));
        }
    };

    // ---- ldmatrix lane address components (2x4 warp grid, warptile 64x32)
    const int wm   = wid >> 2;     // 0..1  (M)
    const int wn   = wid & 3;      // 0..3  (N)
    const int wrot = wid & 3;      // per-warp ks rotation (deconvoy)
    const uint32_t a_row  = (uint32_t)(wm * 64 + (lane & 15));
    const uint32_t a_cadd = (uint32_t)(lane >> 4);
    const uint32_t b_row  = (uint32_t)(wn * 32 + ((lane >> 4) << 3) + (lane & 7));
    const uint32_t b_cadd = (uint32_t)((lane >> 3) & 1);

    float c[4][4][4];

    // one ks slice (k16): 6 ldsm.x4 feeding 16 MMAs
    auto do_ks = [&](uint32_t as, uint32_t bs, int ks) {
        const uint32_t ac = 2 * (uint32_t)ks + a_cadd;
        const uint32_t bc = 2 * (uint32_t)ks + b_cadd;
        uint32_t a[4][4];
#pragma unroll
        for (int m = 0; m < 4; ++m)
            ldsm_x4(a[m], as + sw128((a_row + m * 16) * 128u + ac * 16u));
        uint32_t bq[8];
        ldsm_x4(bq + 0, bs + sw128((b_row +  0) * 128u + bc * 16u));
        ldsm_x4(bq + 4, bs + sw128((b_row + 16) * 128u + bc * 16u));
#pragma unroll
        for (int m = 0; m < 4; ++m)
#pragma unroll
            for (int q = 0; q < 4; ++q)
                mma_f16(c[m][q], a[m], bq[2 * q], bq[2 * q + 1]);
    };

    // =======================================================================
    for (int t = 0; t < 2; ++t) {
        const int o_base = o_base0 + t * TILE_N;
        const __half* b_srcT = b_src0 + (size_t)t * TILE_N * DIN;

#pragma unroll
        for (int i = 0; i < 4; ++i)
#pragma unroll
            for (int j = 0; j < 4; ++j)
#pragma unroll
                for (int k = 0; k < 4; ++k) c[i][j][k] = 0.0f;

        if (t == 0) {
            // cold prologue: fill stages 0 and 1 (B async, A ldg+cvt+sts)
            float4 v[8];
            issue_b(0, 0, b_srcT);
            issue_b(1, 1, b_srcT);
            ldg_a(v, 0);
            sts_a(0, v);
            ldg_a(v, 1);
            sts_a(1, v);
            cp_wait<0>();
            __syncthreads();
        }
        // (t == 1: stages 0,1 were refilled during tile 0's epilogue)

        int s = 0;
        for (int kc = 0; kc < K_ITERS; ++kc) {
            const int s_issue = (s + 2 >= STAGES) ? s + 2 - STAGES : s + 2;
            const uint32_t as = sbase + s * STAGE_BYTES;
            const uint32_t bs = as + A_BYTES;
            const bool pre = (kc + 2 < K_ITERS);

            float4 v[8];
            if (pre) {
                issue_b(s_issue, kc + 2, b_srcT);
                ldg_a(v, kc + 2);           // held across the 4-ks window
            }

            do_ks(as, bs, (0 + wrot) & 3);
            do_ks(as, bs, (1 + wrot) & 3);
            do_ks(as, bs, (2 + wrot) & 3);
            do_ks(as, bs, (3 + wrot) & 3);

            if (pre) sts_a(s_issue, v);     // cvt + store A for stage kc+2

            if (kc + 1 < K_ITERS) {
                if (pre) cp_wait<1>(); else cp_wait<0>();
                __syncthreads();
            }
            s = (s + 1 == STAGES) ? 0 : s + 1;
        }

        // publish stage buffers as free before refilling for the next tile
        __syncthreads();

        // ---- epilogue, interleaved with next tile's stage-0/1 refill
        const float* bsm = reinterpret_cast<const float*>(smem + SMEM_BIAS) + t * TILE_N;
        const int r_top = m_base + wm * 64 + (lane >> 2);
        const int lc0   = wn * 32 + (lane & 3) * 2;

        float4 v[8];
        if (t == 0) {
            const __half* b_srcN = b_src0 + (size_t)TILE_N * DIN;
            issue_b(0, 0, b_srcN);
            issue_b(1, 1, b_srcN);
            ldg_a(v, 0);                    // A identical for both tiles
        }

#pragma unroll
        for (int m = 0; m < 4; ++m) {
#pragma unroll
            for (int q = 0; q < 4; ++q) {
                const int lc = lc0 + q * 8;
                const float b0 = bsm[lc], b1 = bsm[lc + 1];
                float* d0 = out + (size_t)(r_top + m * 16) * OUT_W + n * DOUT + o_base + lc;
                float* d1 = d0 + 8 * OUT_W;
                float2 v0 = { c[m][q][0] + b0, c[m][q][1] + b1 };
                float2 v1 = { c[m][q][2] + b0, c[m][q][3] + b1 };
                *reinterpret_cast<float2*>(d0) = v0;
                *reinterpret_cast<float2*>(d1) = v1;
            }
            if (t == 0 && m == 1) {
                sts_a(0, v);                // stage 0 A landed under m=0..1 STGs
                ldg_a(v, 1);
            }
        }
        if (t == 0) {
            sts_a(1, v);
            cp_wait<0>();                   // next tile's B stages landed
            __syncthreads();
        }
    }
}

// ---------------------------------------------------------------------------
extern "C" void kernel_launch(void* const* d_in, const int* in_sizes, int n_in,
                              void* d_out, int out_size) {
    const float* x = (const float*)d_in[0];
    const float* W = (const float*)d_in[1];
    const float* b = (const float*)d_in[2];
    float* out = (float*)d_out;

    cudaFuncSetAttribute(node_gemm_kernel,
                         cudaFuncAttributeMaxDynamicSharedMemorySize, SMEM_TOTAL);

    wt_transpose_kernel<<<dim3(DIN / 32, DOUT / 32, N_NODES), dim3(32, 8)>>>(W);

    const int grid = N_NODES * (B_DIM / TILE_M) * 2;   // 64*16*2 = 2048
    node_gemm_kernel<<<grid, THREADS, SMEM_TOTAL>>>(x, b, out);
}

// round 13
// speedup vs baseline: 1.3335x; 1.3335x over previous
#include <cuda_runtime.h>
#include <cuda_fp16.h>
#include <cstdint>

// ---------------------------------------------------------------------------
// NodePredictor: y[b,n,:] = x[b,n,:] @ W[n] + b[n], out = y reshaped [B, N*DOUT]
// B=2048, N=64, DIN=DOUT=512, fp32. sm_100 legacy path.
//
// R13 = R11 (fp16 m16n8k16, both operands pre-converted, 2 tiles/CTA,
// 3-stage cp.async) +
//  - A-fragment register double-buffering: next-ks A ldsm issued before the
//    current MMA burst -> ldsm latency hidden under tensor backlog (R11
//    showed tensor and L1 serialized ~126us+126us; this overlaps them).
//  - prepasses merged into ONE kernel (wt transpose hides under the x
//    conversion's DRAM stream).
// ---------------------------------------------------------------------------

static constexpr int B_DIM   = 2048;
static constexpr int N_NODES = 64;
static constexpr int DIN     = 512;
static constexpr int DOUT    = 512;
static constexpr int OUT_W   = N_NODES * DOUT;   // 32768

static constexpr int TILE_M  = 128;
static constexpr int TILE_N  = 128;
static constexpr int TILE_K  = 64;               // 64 halfs = 128 B row
static constexpr int K_ITERS = DIN / TILE_K;     // 8
static constexpr int THREADS = 256;
static constexpr int STAGES  = 3;

static constexpr int A_BYTES = TILE_M * 128;     // 16 KB
static constexpr int STAGE_BYTES = 32768;        // A 16KB + B 16KB
static constexpr int SMEM_BIAS   = STAGES * STAGE_BYTES;          // 98304
static constexpr int SMEM_TOTAL  = SMEM_BIAS + 2 * TILE_N * 4;    // 99328

// prepass grid split
static constexpr int X_BLOCKS  = (int)((size_t)B_DIM * N_NODES * DIN / 8 / 256); // 32768
static constexpr int WT_BLOCKS = (DIN / 32) * (DOUT / 32) * N_NODES;             // 16384

// scratch: x and W^T pre-converted to fp16 (RNE)
__device__ __half g_Xh[(size_t)B_DIM * N_NODES * DIN];            // 128 MB
__device__ __half g_Wh[(size_t)N_NODES * DOUT * DIN];             // 32 MB

// ---------------------------------------------------------------------------
__device__ __forceinline__ uint32_t smem_u32(const void* p) {
    uint32_t a;
    asm("{ .reg .u64 t; cvta.to.shared.u64 t, %1; cvt.u32.u64 %0, t; }" : "=r"(a) : "l"(p));
    return a;
}
__device__ __forceinline__ uint32_t sw128(uint32_t off) {
    return off ^ ((off >> 3) & 0x70u);
}
__device__ __forceinline__ uint32_t h2(float a, float b) {
    __half2 h = __floats2half2_rn(a, b);
    return *reinterpret_cast<uint32_t*>(&h);
}
__device__ __forceinline__ void cp_async16(uint32_t smem_dst, const void* gmem_src) {
    asm volatile("cp.async.cg.shared.global [%0], [%1], 16;"
                 :: "r"(smem_dst), "l"(gmem_src) : "memory");
}
__device__ __forceinline__ void cp_commit() {
    asm volatile("cp.async.commit_group;" ::: "memory");
}
template <int N>
__device__ __forceinline__ void cp_wait() {
    asm volatile("cp.async.wait_group %0;" :: "n"(N) : "memory");
}
__device__ __forceinline__ void ldsm_x4(uint32_t* r, uint32_t addr) {
    asm volatile("ldmatrix.sync.aligned.m8n8.x4.shared.b16 {%0,%1,%2,%3}, [%4];"
                 : "=r"(r[0]), "=r"(r[1]), "=r"(r[2]), "=r"(r[3]) : "r"(addr));
}
__device__ __forceinline__ void mma_f16(float* c, const uint32_t* a, uint32_t b0, uint32_t b1) {
    asm volatile(
        "mma.sync.aligned.m16n8k16.row.col.f32.f16.f16.f32 "
        "{%0,%1,%2,%3}, {%4,%5,%6,%7}, {%8,%9}, {%0,%1,%2,%3};"
        : "+f"(c[0]), "+f"(c[1]), "+f"(c[2]), "+f"(c[3])
        : "r"(a[0]), "r"(a[1]), "r"(a[2]), "r"(a[3]), "r"(b0), "r"(b1));
}

// ---------------------------------------------------------------------------
// Merged pre-pass: blocks [0, X_BLOCKS) convert x -> g_Xh (fp16, RNE),
// blocks [X_BLOCKS, X_BLOCKS+WT_BLOCKS) transpose+convert W -> g_Wh.
// ---------------------------------------------------------------------------
__global__ void prep_kernel(const float* __restrict__ x, const float* __restrict__ W) {
    __shared__ float tile[32][33];
    if (blockIdx.x < (unsigned)X_BLOCKS) {
        // x conversion: each thread reads 2 float4 (32B), writes uint4 (16B)
        const size_t gi = (size_t)blockIdx.x * 256 + threadIdx.x;
        const float4 v0 = reinterpret_cast<const float4*>(x)[2 * gi];
        const float4 v1 = reinterpret_cast<const float4*>(x)[2 * gi + 1];
        uint4 o;
        o.x = h2(v0.x, v0.y);
        o.y = h2(v0.z, v0.w);
        o.z = h2(v1.x, v1.y);
        o.w = h2(v1.z, v1.w);
        reinterpret_cast<uint4*>(g_Xh)[gi] = o;
    } else {
        // W transpose: g_Wh[n][o][i] = half(W[n][i][o])
        const int bid = blockIdx.x - X_BLOCKS;
        const int ix = bid & 15;
        const int oy = (bid >> 4) & 15;
        const int n  = bid >> 8;
        const int i0 = ix * 32;
        const int o0 = oy * 32;
        const int tx = threadIdx.x & 31, ty = threadIdx.x >> 5;   // 32 x 8

        const float* src = W + ((size_t)n * DIN + i0) * DOUT + o0;
#pragma unroll
        for (int r = 0; r < 32; r += 8)
            tile[ty + r][tx] = src[(size_t)(ty + r) * DOUT + tx];
        __syncthreads();

        __half* dst = g_Wh + ((size_t)n * DOUT + o0) * DIN + i0;
#pragma unroll
        for (int r = 0; r < 32; r += 8)
            dst[(size_t)(ty + r) * DIN + tx] = __float2half_rn(tile[tx][ty + r]);
    }
}

// ---------------------------------------------------------------------------
// Main GEMM: CTA handles TWO [128M x 128N] tiles (same node+mt, nt pair).
// 8 warps 2x4, warptile 64x32, fp16 MMA m16n8k16, A-frag double buffering.
// ---------------------------------------------------------------------------
__global__ __launch_bounds__(THREADS, 2)
void node_gemm_kernel(const float* __restrict__ bias, float* __restrict__ out) {
    extern __shared__ char smem[];
    const uint32_t sbase = smem_u32(smem);
    const int tid  = threadIdx.x;
    const int wid  = tid >> 5;
    const int lane = tid & 31;

    // block decode: ntp fastest, then mt, then node
    const int bx  = blockIdx.x;
    const int n   = bx >> 5;
    const int mt  = (bx >> 1) & 15;
    const int ntp = bx & 1;                 // nt pair: tiles ntp*2, ntp*2+1
    const int m_base  = mt * TILE_M;
    const int o_base0 = (ntp * 2) * TILE_N;

    // both tiles' biases -> smem
    {
        const int t = tid >> 7;             // 0 or 1
        const int c = tid & 127;
        reinterpret_cast<float*>(smem + SMEM_BIAS)[t * TILE_N + c] =
            bias[n * DOUT + o_base0 + t * TILE_N + c];
    }

    // ---- staging: thread t -> row t/2, 16B-chunks (t&1)*4..+3 (8 halfs each)
    const int st_row = tid >> 1;
    const int st_cb  = (tid & 1) * 4;
    const __half* a_src = g_Xh + ((size_t)(m_base + st_row) * N_NODES + n) * DIN + st_cb * 8;
    const __half* b_src0 = g_Wh + ((size_t)(n * DOUT + o_base0 + st_row)) * DIN + st_cb * 8;
    uint32_t st_dst[4];
#pragma unroll
    for (int j = 0; j < 4; ++j)
        st_dst[j] = sw128((uint32_t)st_row * 128u + (uint32_t)(st_cb + j) * 16u);

    // one commit group per stage: 4x16B A + 4x16B B (both fp16)
    auto issue = [&](int stage, int kc, const __half* b_src) {
        const uint32_t as = sbase + stage * STAGE_BYTES;
        const uint32_t bs = as + A_BYTES;
        const __half* ap = a_src + kc * TILE_K;
        const __half* bp = b_src + kc * TILE_K;
#pragma unroll
        for (int j = 0; j < 4; ++j) cp_async16(as + st_dst[j], ap + j * 8);
#pragma unroll
        for (int j = 0; j < 4; ++j) cp_async16(bs + st_dst[j], bp + j * 8);
        cp_commit();
    };

    // ---- ldmatrix lane address components (2x4 warp grid, warptile 64x32)
    const int wm = wid >> 2;       // 0..1  (M)
    const int wn = wid & 3;        // 0..3  (N)
    const uint32_t a_row  = (uint32_t)(wm * 64 + (lane & 15));
    const uint32_t a_cadd = (uint32_t)(lane >> 4);
    const uint32_t b_row  = (uint32_t)(wn * 32 + ((lane >> 4) << 3) + (lane & 7));
    const uint32_t b_cadd = (uint32_t)((lane >> 3) & 1);

    uint32_t af[2][4][4];          // double-buffered A fragments
    uint32_t bq[8];                // B fragments (current ks)
    float c[4][4][4];

    auto ldsm_a_all = [&](uint32_t (&a)[4][4], uint32_t as, int ks) {
        const uint32_t ac = 2 * (uint32_t)ks + a_cadd;
#pragma unroll
        for (int m = 0; m < 4; ++m)
            ldsm_x4(a[m], as + sw128((a_row + m * 16) * 128u + ac * 16u));
    };
    auto ldsm_b_all = [&](uint32_t bs, int ks) {
        const uint32_t bc = 2 * (uint32_t)ks + b_cadd;
        ldsm_x4(bq + 0, bs + sw128((b_row +  0) * 128u + bc * 16u));
        ldsm_x4(bq + 4, bs + sw128((b_row + 16) * 128u + bc * 16u));
    };
    auto mma16 = [&](const uint32_t (&a)[4][4]) {
#pragma unroll
        for (int m = 0; m < 4; ++m)
#pragma unroll
            for (int q = 0; q < 4; ++q)
                mma_f16(c[m][q], a[m], bq[2 * q], bq[2 * q + 1]);
    };

    // =======================================================================
    for (int t = 0; t < 2; ++t) {
        const int o_base = o_base0 + t * TILE_N;
        const __half* b_srcT = b_src0 + (size_t)t * TILE_N * DIN;

#pragma unroll
        for (int i = 0; i < 4; ++i)
#pragma unroll
            for (int j = 0; j < 4; ++j)
#pragma unroll
                for (int k = 0; k < 4; ++k) c[i][j][k] = 0.0f;

        if (t == 0) {
            issue(0, 0, b_srcT);
            issue(1, 1, b_srcT);
            cp_wait<1>();
            __syncthreads();
        }
        // (t == 1: stages 0,1 were filled during tile 0's epilogue)

        int s = 0;
        for (int kc = 0; kc < K_ITERS; ++kc) {
            const int s_issue = (s + 2 >= STAGES) ? s + 2 - STAGES : s + 2;
            const uint32_t as = sbase + s * STAGE_BYTES;
            const uint32_t bs = as + A_BYTES;
            const bool pre = (kc + 2 < K_ITERS);

            // software-pipelined ks: A(ks+1) issued before MMA(ks)
            ldsm_a_all(af[0], as, 0);
            ldsm_b_all(bs, 0);
            ldsm_a_all(af[1], as, 1);
            if (pre) issue(s_issue, kc + 2, b_srcT);
            mma16(af[0]);

            ldsm_b_all(bs, 1);
            ldsm_a_all(af[0], as, 2);
            mma16(af[1]);

            ldsm_b_all(bs, 2);
            ldsm_a_all(af[1], as, 3);
            mma16(af[0]);

            ldsm_b_all(bs, 3);
            mma16(af[1]);

            if (kc + 1 < K_ITERS) {
                if (pre) cp_wait<1>(); else cp_wait<0>();
                __syncthreads();
            }
            s = (s + 1 == STAGES) ? 0 : s + 1;
        }

        // publish stage buffers as free before refilling for the next tile
        __syncthreads();

        if (t == 0) {
            // fill next tile's stages 0,1 NOW -> overlaps the epilogue STGs
            const __half* b_srcN = b_src0 + (size_t)TILE_N * DIN;
            issue(0, 0, b_srcN);
            issue(1, 1, b_srcN);
        }

        // ---- epilogue: add bias, store (c0,c1)/(c2,c3) as float2
        const float* bsm = reinterpret_cast<const float*>(smem + SMEM_BIAS) + t * TILE_N;
        const int r_top = m_base + wm * 64 + (lane >> 2);
        const int lc0   = wn * 32 + (lane & 3) * 2;
#pragma unroll
        for (int m = 0; m < 4; ++m) {
#pragma unroll
            for (int q = 0; q < 4; ++q) {
                const int lc = lc0 + q * 8;
                const float b0 = bsm[lc], b1 = bsm[lc + 1];
                float* d0 = out + (size_t)(r_top + m * 16) * OUT_W + n * DOUT + o_base + lc;
                float* d1 = d0 + 8 * OUT_W;
                float2 v0 = { c[m][q][0] + b0, c[m][q][1] + b1 };
                float2 v1 = { c[m][q][2] + b0, c[m][q][3] + b1 };
                *reinterpret_cast<float2*>(d0) = v0;
                *reinterpret_cast<float2*>(d1) = v1;
            }
        }

        if (t == 0) {
            cp_wait<0>();       // next tile's stages 0,1 landed
            __syncthreads();
        }
    }
}

// ---------------------------------------------------------------------------
extern "C" void kernel_launch(void* const* d_in, const int* in_sizes, int n_in,
                              void* d_out, int out_size) {
    const float* x = (const float*)d_in[0];
    const float* W = (const float*)d_in[1];
    const float* b = (const float*)d_in[2];
    float* out = (float*)d_out;

    cudaFuncSetAttribute(node_gemm_kernel,
                         cudaFuncAttributeMaxDynamicSharedMemorySize, SMEM_TOTAL);

    prep_kernel<<<X_BLOCKS + WT_BLOCKS, 256>>>(x, W);

    const int grid = N_NODES * (B_DIM / TILE_M) * 2;   // 64*16*2 = 2048
    node_gemm_kernel<<<grid, THREADS, SMEM_TOTAL>>>(b, out);
}

// round 14
// speedup vs baseline: 1.5001x; 1.1249x over previous
#include <cuda_runtime.h>
#include <cuda_fp16.h>
#include <cstdint>

// ---------------------------------------------------------------------------
// NodePredictor: y[b,n,:] = x[b,n,:] @ W[n] + b[n], out = y reshaped [B, N*DOUT]
// B=2048, N=64, DIN=DOUT=512, fp32. sm_100 legacy path.
//
// R14 = exact R11 GEMM (measured 265us: fp16 m16n8k16, do_ks ordering,
// per-warp ks rotation, 2 tiles/CTA, 3-stage cp.async, single-buffered frags)
// + R13's merged single-launch prepass (measured 67us: x->fp16 conversion
// blocks + W-transpose blocks in one grid).
// ---------------------------------------------------------------------------

static constexpr int B_DIM   = 2048;
static constexpr int N_NODES = 64;
static constexpr int DIN     = 512;
static constexpr int DOUT    = 512;
static constexpr int OUT_W   = N_NODES * DOUT;   // 32768

static constexpr int TILE_M  = 128;
static constexpr int TILE_N  = 128;
static constexpr int TILE_K  = 64;               // 64 halfs = 128 B row
static constexpr int K_ITERS = DIN / TILE_K;     // 8
static constexpr int THREADS = 256;
static constexpr int STAGES  = 3;

static constexpr int A_BYTES = TILE_M * 128;     // 16 KB
static constexpr int STAGE_BYTES = 32768;        // A 16KB + B 16KB
static constexpr int SMEM_BIAS   = STAGES * STAGE_BYTES;          // 98304
static constexpr int SMEM_TOTAL  = SMEM_BIAS + 2 * TILE_N * 4;    // 99328

// prepass grid split
static constexpr int X_BLOCKS  = (int)((size_t)B_DIM * N_NODES * DIN / 8 / 256); // 32768
static constexpr int WT_BLOCKS = (DIN / 32) * (DOUT / 32) * N_NODES;             // 16384

// scratch: x and W^T pre-converted to fp16 (RNE)
__device__ __half g_Xh[(size_t)B_DIM * N_NODES * DIN];            // 128 MB
__device__ __half g_Wh[(size_t)N_NODES * DOUT * DIN];             // 32 MB

// ---------------------------------------------------------------------------
__device__ __forceinline__ uint32_t smem_u32(const void* p) {
    uint32_t a;
    asm("{ .reg .u64 t; cvta.to.shared.u64 t, %1; cvt.u32.u64 %0, t; }" : "=r"(a) : "l"(p));
    return a;
}
__device__ __forceinline__ uint32_t sw128(uint32_t off) {
    return off ^ ((off >> 3) & 0x70u);
}
__device__ __forceinline__ uint32_t h2(float a, float b) {
    __half2 h = __floats2half2_rn(a, b);
    return *reinterpret_cast<uint32_t*>(&h);
}
__device__ __forceinline__ void cp_async16(uint32_t smem_dst, const void* gmem_src) {
    asm volatile("cp.async.cg.shared.global [%0], [%1], 16;"
                 :: "r"(smem_dst), "l"(gmem_src) : "memory");
}
__device__ __forceinline__ void cp_commit() {
    asm volatile("cp.async.commit_group;" ::: "memory");
}
template <int N>
__device__ __forceinline__ void cp_wait() {
    asm volatile("cp.async.wait_group %0;" :: "n"(N) : "memory");
}
__device__ __forceinline__ void ldsm_x4(uint32_t* r, uint32_t addr) {
    asm volatile("ldmatrix.sync.aligned.m8n8.x4.shared.b16 {%0,%1,%2,%3}, [%4];"
                 : "=r"(r[0]), "=r"(r[1]), "=r"(r[2]), "=r"(r[3]) : "r"(addr));
}
__device__ __forceinline__ void mma_f16(float* c, const uint32_t* a, uint32_t b0, uint32_t b1) {
    asm volatile(
        "mma.sync.aligned.m16n8k16.row.col.f32.f16.f16.f32 "
        "{%0,%1,%2,%3}, {%4,%5,%6,%7}, {%8,%9}, {%0,%1,%2,%3};"
        : "+f"(c[0]), "+f"(c[1]), "+f"(c[2]), "+f"(c[3])
        : "r"(a[0]), "r"(a[1]), "r"(a[2]), "r"(a[3]), "r"(b0), "r"(b1));
}

// ---------------------------------------------------------------------------
// Merged pre-pass: blocks [0, X_BLOCKS) convert x -> g_Xh (fp16, RNE),
// blocks [X_BLOCKS, X_BLOCKS+WT_BLOCKS) transpose+convert W -> g_Wh.
// ---------------------------------------------------------------------------
__global__ void prep_kernel(const float* __restrict__ x, const float* __restrict__ W) {
    __shared__ float tile[32][33];
    if (blockIdx.x < (unsigned)X_BLOCKS) {
        // x conversion: each thread reads 2 float4 (32B), writes uint4 (16B)
        const size_t gi = (size_t)blockIdx.x * 256 + threadIdx.x;
        const float4 v0 = reinterpret_cast<const float4*>(x)[2 * gi];
        const float4 v1 = reinterpret_cast<const float4*>(x)[2 * gi + 1];
        uint4 o;
        o.x = h2(v0.x, v0.y);
        o.y = h2(v0.z, v0.w);
        o.z = h2(v1.x, v1.y);
        o.w = h2(v1.z, v1.w);
        reinterpret_cast<uint4*>(g_Xh)[gi] = o;
    } else {
        // W transpose: g_Wh[n][o][i] = half(W[n][i][o])
        const int bid = blockIdx.x - X_BLOCKS;
        const int ix = bid & 15;
        const int oy = (bid >> 4) & 15;
        const int n  = bid >> 8;
        const int i0 = ix * 32;
        const int o0 = oy * 32;
        const int tx = threadIdx.x & 31, ty = threadIdx.x >> 5;   // 32 x 8

        const float* src = W + ((size_t)n * DIN + i0) * DOUT + o0;
#pragma unroll
        for (int r = 0; r < 32; r += 8)
            tile[ty + r][tx] = src[(size_t)(ty + r) * DOUT + tx];
        __syncthreads();

        __half* dst = g_Wh + ((size_t)n * DOUT + o0) * DIN + i0;
#pragma unroll
        for (int r = 0; r < 32; r += 8)
            dst[(size_t)(ty + r) * DIN + tx] = __float2half_rn(tile[tx][ty + r]);
    }
}

// ---------------------------------------------------------------------------
// Main GEMM: CTA handles TWO [128M x 128N] tiles (same node+mt, nt pair).
// 8 warps 2x4, warptile 64x32, fp16 MMA m16n8k16. Exact R11 structure.
// ---------------------------------------------------------------------------
__global__ __launch_bounds__(THREADS, 2)
void node_gemm_kernel(const float* __restrict__ bias, float* __restrict__ out) {
    extern __shared__ char smem[];
    const uint32_t sbase = smem_u32(smem);
    const int tid  = threadIdx.x;
    const int wid  = tid >> 5;
    const int lane = tid & 31;

    // block decode: ntp fastest, then mt, then node
    const int bx  = blockIdx.x;
    const int n   = bx >> 5;
    const int mt  = (bx >> 1) & 15;
    const int ntp = bx & 1;                 // nt pair: tiles ntp*2, ntp*2+1
    const int m_base  = mt * TILE_M;
    const int o_base0 = (ntp * 2) * TILE_N;

    // both tiles' biases -> smem
    {
        const int t = tid >> 7;             // 0 or 1
        const int c = tid & 127;
        reinterpret_cast<float*>(smem + SMEM_BIAS)[t * TILE_N + c] =
            bias[n * DOUT + o_base0 + t * TILE_N + c];
    }

    // ---- staging: thread t -> row t/2, 16B-chunks (t&1)*4..+3 (8 halfs each)
    const int st_row = tid >> 1;
    const int st_cb  = (tid & 1) * 4;
    const __half* a_src = g_Xh + ((size_t)(m_base + st_row) * N_NODES + n) * DIN + st_cb * 8;
    const __half* b_src0 = g_Wh + ((size_t)(n * DOUT + o_base0 + st_row)) * DIN + st_cb * 8;
    uint32_t st_dst[4];
#pragma unroll
    for (int j = 0; j < 4; ++j)
        st_dst[j] = sw128((uint32_t)st_row * 128u + (uint32_t)(st_cb + j) * 16u);

    // one commit group per stage: 4x16B A + 4x16B B (both fp16)
    auto issue = [&](int stage, int kc, const __half* b_src) {
        const uint32_t as = sbase + stage * STAGE_BYTES;
        const uint32_t bs = as + A_BYTES;
        const __half* ap = a_src + kc * TILE_K;
        const __half* bp = b_src + kc * TILE_K;
#pragma unroll
        for (int j = 0; j < 4; ++j) cp_async16(as + st_dst[j], ap + j * 8);
#pragma unroll
        for (int j = 0; j < 4; ++j) cp_async16(bs + st_dst[j], bp + j * 8);
        cp_commit();
    };

    // ---- ldmatrix lane address components (2x4 warp grid, warptile 64x32)
    const int wm   = wid >> 2;     // 0..1  (M)
    const int wn   = wid & 3;      // 0..3  (N)
    const int wrot = wid & 3;      // per-warp ks rotation (deconvoy)
    const uint32_t a_row  = (uint32_t)(wm * 64 + (lane & 15));
    const uint32_t a_cadd = (uint32_t)(lane >> 4);
    const uint32_t b_row  = (uint32_t)(wn * 32 + ((lane >> 4) << 3) + (lane & 7));
    const uint32_t b_cadd = (uint32_t)((lane >> 3) & 1);

    float c[4][4][4];

    // one ks slice (k16): 6 ldsm.x4 feeding 16 MMAs
    auto do_ks = [&](uint32_t as, uint32_t bs, int ks) {
        const uint32_t ac = 2 * (uint32_t)ks + a_cadd;
        const uint32_t bc = 2 * (uint32_t)ks + b_cadd;
        uint32_t a[4][4];
#pragma unroll
        for (int m = 0; m < 4; ++m)
            ldsm_x4(a[m], as + sw128((a_row + m * 16) * 128u + ac * 16u));
        uint32_t bq[8];
        ldsm_x4(bq + 0, bs + sw128((b_row +  0) * 128u + bc * 16u));
        ldsm_x4(bq + 4, bs + sw128((b_row + 16) * 128u + bc * 16u));
#pragma unroll
        for (int m = 0; m < 4; ++m)
#pragma unroll
            for (int q = 0; q < 4; ++q)
                mma_f16(c[m][q], a[m], bq[2 * q], bq[2 * q + 1]);
    };

    // =======================================================================
    for (int t = 0; t < 2; ++t) {
        const int o_base = o_base0 + t * TILE_N;
        const __half* b_srcT = b_src0 + (size_t)t * TILE_N * DIN;

#pragma unroll
        for (int i = 0; i < 4; ++i)
#pragma unroll
            for (int j = 0; j < 4; ++j)
#pragma unroll
                for (int k = 0; k < 4; ++k) c[i][j][k] = 0.0f;

        if (t == 0) {
            // cold prologue: fill stages 0 and 1
            issue(0, 0, b_srcT);
            issue(1, 1, b_srcT);
            cp_wait<1>();
            __syncthreads();
        }
        // (t == 1: stages 0,1 were filled during tile 0's epilogue)

        int s = 0;
        for (int kc = 0; kc < K_ITERS; ++kc) {
            const int s_issue = (s + 2 >= STAGES) ? s + 2 - STAGES : s + 2;
            const uint32_t as = sbase + s * STAGE_BYTES;
            const uint32_t bs = as + A_BYTES;
            const bool pre = (kc + 2 < K_ITERS);

            // ks order rotated per warp; staging issued after the first slice
            do_ks(as, bs, (0 + wrot) & 3);
            if (pre) issue(s_issue, kc + 2, b_srcT);
            do_ks(as, bs, (1 + wrot) & 3);
            do_ks(as, bs, (2 + wrot) & 3);
            do_ks(as, bs, (3 + wrot) & 3);

            if (kc + 1 < K_ITERS) {
                if (pre) cp_wait<1>(); else cp_wait<0>();
                __syncthreads();
            }
            s = (s + 1 == STAGES) ? 0 : s + 1;
        }

        // publish stage buffers as free before refilling for the next tile
        __syncthreads();

        if (t == 0) {
            // fill next tile's stages 0,1 NOW -> overlaps the epilogue STGs
            const __half* b_srcN = b_src0 + (size_t)TILE_N * DIN;
            issue(0, 0, b_srcN);
            issue(1, 1, b_srcN);
        }

        // ---- epilogue: add bias, store (c0,c1)/(c2,c3) as float2
        const float* bsm = reinterpret_cast<const float*>(smem + SMEM_BIAS) + t * TILE_N;
        const int r_top = m_base + wm * 64 + (lane >> 2);
        const int lc0   = wn * 32 + (lane & 3) * 2;
#pragma unroll
        for (int m = 0; m < 4; ++m) {
#pragma unroll
            for (int q = 0; q < 4; ++q) {
                const int lc = lc0 + q * 8;
                const float b0 = bsm[lc], b1 = bsm[lc + 1];
                float* d0 = out + (size_t)(r_top + m * 16) * OUT_W + n * DOUT + o_base + lc;
                float* d1 = d0 + 8 * OUT_W;
                float2 v0 = { c[m][q][0] + b0, c[m][q][1] + b1 };
                float2 v1 = { c[m][q][2] + b0, c[m][q][3] + b1 };
                *reinterpret_cast<float2*>(d0) = v0;
                *reinterpret_cast<float2*>(d1) = v1;
            }
        }

        if (t == 0) {
            cp_wait<0>();       // next tile's stages 0,1 landed
            __syncthreads();
        }
    }
}

// ---------------------------------------------------------------------------
extern "C" void kernel_launch(void* const* d_in, const int* in_sizes, int n_in,
                              void* d_out, int out_size) {
    const float* x = (const float*)d_in[0];
    const float* W = (const float*)d_in[1];
    const float* b = (const float*)d_in[2];
    float* out = (float*)d_out;

    cudaFuncSetAttribute(node_gemm_kernel,
                         cudaFuncAttributeMaxDynamicSharedMemorySize, SMEM_TOTAL);

    prep_kernel<<<X_BLOCKS + WT_BLOCKS, 256>>>(x, W);

    const int grid = N_NODES * (B_DIM / TILE_M) * 2;   // 64*16*2 = 2048
    node_gemm_kernel<<<grid, THREADS, SMEM_TOTAL>>>(b, out);
}